// round 12
// baseline (speedup 1.0000x reference)
#include <cuda_runtime.h>
#include <cuda_bf16.h>
#include <math.h>
#include <stdint.h>

// ---------------- Problem constants ----------------
#define BB    4
#define TT    1024
#define NTOK  (BB*TT)
#define DD    768
#define HH    12
#define HD    64
#define LL    6
#define VV    32000
#define DFF   3072
#define DQKV  2304
#define EPS   1e-5f
#define NSPLIT 8

// ---------------- Static device buffers ------------
__device__ float g_h   [NTOK * DD];
__device__ float g_qkv [NTOK * DQKV];
__device__ __nv_bfloat16 g_xh[NTOK*DD],  g_xl[NTOK*DD];
__device__ __nv_bfloat16 g_ah[NTOK*DD],  g_al[NTOK*DD];
__device__ __nv_bfloat16 g_fh[NTOK*DFF], g_fl[NTOK*DFF];
__device__ float g_pacc[(size_t)NSPLIT * NTOK * DD];
__device__ float g_pm  [(size_t)NSPLIT * NTOK * HH];
__device__ float g_pl  [(size_t)NSPLIT * NTOK * HH];
__device__ __nv_bfloat16 w_qkvh[LL*DQKV*DD], w_qkvl[LL*DQKV*DD];
__device__ __nv_bfloat16 w_fch [LL*DD*DD],   w_fcl [LL*DD*DD];
__device__ __nv_bfloat16 w_f1h [LL*DFF*DD],  w_f1l [LL*DFF*DD];
__device__ __nv_bfloat16 w_f2h [LL*DD*DFF],  w_f2l [LL*DD*DFF];
__device__ __nv_bfloat16 w_oh  [VV*DD],      w_ol  [VV*DD];

// ---------------- PTX helpers ----------------------
__device__ __forceinline__ uint32_t smem_to_u32(const void* p) {
    uint32_t a;
    asm("{ .reg .u64 t; cvta.to.shared.u64 t, %1; cvt.u32.u64 %0, t; }"
        : "=r"(a) : "l"(p));
    return a;
}
#define CP_ASYNC16(dst, src) \
    asm volatile("cp.async.cg.shared.global [%0], [%1], 16;" :: "r"(dst), "l"(src))
#define CP_COMMIT asm volatile("cp.async.commit_group;" ::: "memory")
#define CP_WAIT1  asm volatile("cp.async.wait_group 1;" ::: "memory")
#define CP_WAIT0  asm volatile("cp.async.wait_group 0;" ::: "memory")

__device__ __forceinline__ void ldsm4(uint32_t* r, uint32_t addr) {
    asm volatile("ldmatrix.sync.aligned.m8n8.x4.shared.b16 {%0,%1,%2,%3}, [%4];"
        : "=r"(r[0]), "=r"(r[1]), "=r"(r[2]), "=r"(r[3]) : "r"(addr));
}
__device__ __forceinline__ void ldsm2(uint32_t* r, uint32_t addr) {
    asm volatile("ldmatrix.sync.aligned.m8n8.x2.shared.b16 {%0,%1}, [%2];"
        : "=r"(r[0]), "=r"(r[1]) : "r"(addr));
}
__device__ __forceinline__ void mma_bf16(float* d, const uint32_t* a, const uint32_t* b) {
    asm volatile("mma.sync.aligned.m16n8k16.row.col.f32.bf16.bf16.f32 "
        "{%0,%1,%2,%3}, {%4,%5,%6,%7}, {%8,%9}, {%0,%1,%2,%3};"
        : "+f"(d[0]), "+f"(d[1]), "+f"(d[2]), "+f"(d[3])
        : "r"(a[0]), "r"(a[1]), "r"(a[2]), "r"(a[3]), "r"(b[0]), "r"(b[1]));
}

__device__ __forceinline__ float dot4(const float4& a, const float4& b) {
    return fmaf(a.x, b.x, fmaf(a.y, b.y, fmaf(a.z, b.z, a.w * b.w)));
}

// ---------------- Embedding ------------------------
__global__ void embed_kernel(const int* __restrict__ x,
                             const float* __restrict__ tok_emb,
                             const float* __restrict__ pos_emb) {
    int row = blockIdx.x;
    int t   = row % TT;
    int id  = x[row];
    const float* te = tok_emb + (size_t)id * DD;
    const float* pe = pos_emb + (size_t)t  * DD;
    float* out = g_h + (size_t)row * DD;
    for (int i = threadIdx.x; i < DD; i += blockDim.x)
        out[i] = te[i] + pe[i];
}

// ---------------- fp32 -> bf16 hi/lo split ---------
__global__ void cvt_kernel(const float* __restrict__ s,
                           __nv_bfloat16* __restrict__ hi,
                           __nv_bfloat16* __restrict__ lo, int n4) {
    int i = blockIdx.x * blockDim.x + threadIdx.x;
    int stride = gridDim.x * blockDim.x;
    for (; i < n4; i += stride) {
        float4 v = ((const float4*)s)[i];
        __nv_bfloat16 h0 = __float2bfloat16(v.x);
        __nv_bfloat16 h1 = __float2bfloat16(v.y);
        __nv_bfloat16 h2 = __float2bfloat16(v.z);
        __nv_bfloat16 h3 = __float2bfloat16(v.w);
        __nv_bfloat16 l0 = __float2bfloat16(v.x - __bfloat162float(h0));
        __nv_bfloat16 l1 = __float2bfloat16(v.y - __bfloat162float(h1));
        __nv_bfloat16 l2 = __float2bfloat16(v.z - __bfloat162float(h2));
        __nv_bfloat16 l3 = __float2bfloat16(v.w - __bfloat162float(h3));
        __nv_bfloat162* ph = (__nv_bfloat162*)hi + i*2;
        __nv_bfloat162* pl = (__nv_bfloat162*)lo + i*2;
        ph[0] = __nv_bfloat162(h0, h1); ph[1] = __nv_bfloat162(h2, h3);
        pl[0] = __nv_bfloat162(l0, l1); pl[1] = __nv_bfloat162(l2, l3);
    }
}

// ---------------- LayerNorm -> bf16 hi/lo ----------
__device__ __forceinline__ float block_reduce_sum(float v, float* red) {
    int lane = threadIdx.x & 31, wid = threadIdx.x >> 5;
    #pragma unroll
    for (int o = 16; o > 0; o >>= 1) v += __shfl_xor_sync(0xffffffffu, v, o);
    if (lane == 0) red[wid] = v;
    __syncthreads();
    if (wid == 0) {
        float w = (lane < (blockDim.x >> 5)) ? red[lane] : 0.f;
        #pragma unroll
        for (int o = 4; o > 0; o >>= 1) w += __shfl_xor_sync(0xffffffffu, w, o);
        if (lane == 0) red[0] = w;
    }
    __syncthreads();
    float r = red[0];
    __syncthreads();
    return r;
}

__global__ void ln_kernel(const float* __restrict__ xin,
                          const float* __restrict__ sc,
                          const float* __restrict__ bi,
                          __nv_bfloat16* __restrict__ yh,
                          __nv_bfloat16* __restrict__ yl) {
    __shared__ float red[32];
    int row = blockIdx.x;
    const float* xr = xin + (size_t)row * DD;
    float xv[3];
    float s = 0.f;
    #pragma unroll
    for (int i = 0; i < 3; i++) { xv[i] = xr[threadIdx.x + i*256]; s += xv[i]; }
    float mean = block_reduce_sum(s, red) * (1.0f / DD);
    float vs = 0.f;
    #pragma unroll
    for (int i = 0; i < 3; i++) { float d = xv[i] - mean; vs += d * d; }
    float var = block_reduce_sum(vs, red) * (1.0f / DD);
    float rstd = rsqrtf(var + EPS);
    #pragma unroll
    for (int i = 0; i < 3; i++) {
        int c = threadIdx.x + i*256;
        float v = (xv[i] - mean) * rstd * sc[c] + bi[c];
        __nv_bfloat16 h = __float2bfloat16(v);
        yh[(size_t)row*DD + c] = h;
        yl[(size_t)row*DD + c] = __float2bfloat16(v - __bfloat162float(h));
    }
}

// =============== 128x128 HMMA GEMM, KC=32, pitch-80, 2 CTAs/SM =============
// Stage: Ah 10240 | Al 10240 | Wh 10240 | Wl 10240 = 40960; 2 stages = 80KB.
// Pitch 80 = 5x16B groups: (5*row + chunk) mod 8 hits all bank groups -> no swizzle.
#define KC2     32
#define PITCH   80
#define T_AH    0
#define T_AL    10240
#define T_WH    20480
#define T_WL    30720
#define STG2_B  40960
#define GEMM_SMEM (2*STG2_B)

template<int OP>
__global__ __launch_bounds__(256, 2)
void mm_kernel(const __nv_bfloat16* __restrict__ Ah, const __nv_bfloat16* __restrict__ Al,
               const __nv_bfloat16* __restrict__ Wh, const __nv_bfloat16* __restrict__ Wl,
               const float* __restrict__ bias, float* __restrict__ C,
               __nv_bfloat16* __restrict__ Oh, __nv_bfloat16* __restrict__ Ol,
               int N, int K) {
    extern __shared__ char smem[];
    const uint32_t sb = smem_to_u32(smem);
    int tid = threadIdx.x, lane = tid & 31, warp = tid >> 5;
    int wm = warp >> 2;              // 0..1 -> 64 rows
    int wn = warp & 3;               // 0..3 -> 32 cols
    int bm = blockIdx.x * 128, bn = blockIdx.y * 128;

    float acc[4][4][4];
    #pragma unroll
    for (int i = 0; i < 4; i++)
        #pragma unroll
        for (int j = 0; j < 4; j++)
            #pragma unroll
            for (int k = 0; k < 4; k++) acc[i][j][k] = 0.f;

    // loader: thread -> row = tid/2, 2 chunks c0..c0+1 (32B of the 64B row)
    int lrow = tid >> 1;
    int lc0  = (tid & 1) * 2;
    const __nv_bfloat16* gA_h = Ah + (size_t)(bm + lrow) * K + lc0 * 8;
    const __nv_bfloat16* gA_l = Al + (size_t)(bm + lrow) * K + lc0 * 8;
    const __nv_bfloat16* gW_h = Wh + (size_t)(bn + lrow) * K + lc0 * 8;
    const __nv_bfloat16* gW_l = Wl + (size_t)(bn + lrow) * K + lc0 * 8;
    uint32_t lsoff0 = (uint32_t)lrow * PITCH + (uint32_t)lc0 * 16;

    // ldmatrix lane constants (round-3 validated fragment mapping)
    int mat = lane >> 3, r8 = lane & 7;
    int a_kh = mat >> 1;             // 0..1 -> 16B half of the k16
    uint32_t arowb[4];
    #pragma unroll
    for (int ti = 0; ti < 4; ti++) {
        int row = wm*64 + ti*16 + (mat & 1)*8 + r8;
        arowb[ti] = (uint32_t)row * PITCH;
    }
    int bl15 = lane & 15;
    int b_kh = bl15 >> 3;
    uint32_t browb[4];
    #pragma unroll
    for (int ni = 0; ni < 4; ni++) {
        int row = wn*32 + ni*8 + (bl15 & 7);
        browb[ni] = (uint32_t)row * PITCH;
    }

    const int nch = K / KC2;
    {
        uint32_t st = sb;
        #pragma unroll
        for (int i = 0; i < 2; i++) {
            uint32_t so = lsoff0 + i*16;
            CP_ASYNC16(st + T_AH + so, gA_h + i*8);
            CP_ASYNC16(st + T_AL + so, gA_l + i*8);
            CP_ASYNC16(st + T_WH + so, gW_h + i*8);
            CP_ASYNC16(st + T_WL + so, gW_l + i*8);
        }
        CP_COMMIT;
    }

    for (int ch = 0; ch < nch; ch++) {
        if (ch + 1 < nch) {
            uint32_t st = sb + ((ch + 1) & 1) * STG2_B;
            int k0 = (ch + 1) * KC2;
            #pragma unroll
            for (int i = 0; i < 2; i++) {
                uint32_t so = lsoff0 + i*16;
                CP_ASYNC16(st + T_AH + so, gA_h + k0 + i*8);
                CP_ASYNC16(st + T_AL + so, gA_l + k0 + i*8);
                CP_ASYNC16(st + T_WH + so, gW_h + k0 + i*8);
                CP_ASYNC16(st + T_WL + so, gW_l + k0 + i*8);
            }
            CP_COMMIT;
            CP_WAIT1;
        } else {
            CP_WAIT0;
        }
        __syncthreads();

        uint32_t stg = sb + (ch & 1) * STG2_B;
        #pragma unroll
        for (int ks = 0; ks < 2; ks++) {
            uint32_t ahf[4][4], alf[4][4];
            #pragma unroll
            for (int ti = 0; ti < 4; ti++) {
                uint32_t off = arowb[ti] + (uint32_t)((ks*2 + a_kh) << 4);
                ldsm4(ahf[ti], stg + T_AH + off);
                ldsm4(alf[ti], stg + T_AL + off);
            }
            uint32_t bhf[4][2], blf[4][2];
            #pragma unroll
            for (int ni = 0; ni < 4; ni++) {
                uint32_t off = browb[ni] + (uint32_t)((ks*2 + b_kh) << 4);
                ldsm2(bhf[ni], stg + T_WH + off);
                ldsm2(blf[ni], stg + T_WL + off);
            }
            #pragma unroll
            for (int ti = 0; ti < 4; ti++)
                #pragma unroll
                for (int ni = 0; ni < 4; ni++) {
                    mma_bf16(acc[ti][ni], ahf[ti], bhf[ni]);
                    mma_bf16(acc[ti][ni], ahf[ti], blf[ni]);
                    mma_bf16(acc[ti][ni], alf[ti], bhf[ni]);
                }
        }
        __syncthreads();
    }

    int lr = lane >> 2, lc = (lane & 3) * 2;
    #pragma unroll
    for (int ti = 0; ti < 4; ti++) {
        #pragma unroll
        for (int ni = 0; ni < 4; ni++) {
            int grow = bm + wm*64 + ti*16 + lr;
            int gcol = bn + wn*32 + ni*8 + lc;
            #pragma unroll
            for (int half = 0; half < 2; half++) {
                int r = grow + half*8;
                size_t off = (size_t)r * N + gcol;
                float v0 = acc[ti][ni][half*2 + 0];
                float v1 = acc[ti][ni][half*2 + 1];
                if (OP == 0) {
                    *(float2*)&C[off] = make_float2(v0, v1);
                } else if (OP == 1) {
                    *(float2*)&C[off] = make_float2(v0 + bias[gcol], v1 + bias[gcol+1]);
                } else if (OP == 2) {
                    float2 hcur = *(float2*)&C[off];
                    *(float2*)&C[off] = make_float2(v0 + bias[gcol]   + hcur.x,
                                                    v1 + bias[gcol+1] + hcur.y);
                } else {
                    float f0 = fmaxf(v0 + bias[gcol],   0.f);
                    float f1 = fmaxf(v1 + bias[gcol+1], 0.f);
                    __nv_bfloat16 h0 = __float2bfloat16(f0);
                    __nv_bfloat16 h1 = __float2bfloat16(f1);
                    *(__nv_bfloat162*)&Oh[off] = __nv_bfloat162(h0, h1);
                    __nv_bfloat16 l0 = __float2bfloat16(f0 - __bfloat162float(h0));
                    __nv_bfloat16 l1 = __float2bfloat16(f1 - __bfloat162float(h1));
                    *(__nv_bfloat162*)&Ol[off] = __nv_bfloat162(l0, l1);
                }
            }
        }
    }
}

// =============== Causal attention: pair-split + KV-split (S=8) =============
__global__ __launch_bounds__(128)
void attn_kernel(const float* __restrict__ qkv,
                 float* __restrict__ pacc, float* __restrict__ pm,
                 float* __restrict__ pl) {
    __shared__ float4 Ks[1024];
    __shared__ float4 Vs[1024];

    int bh = blockIdx.y;
    int b  = bh / HH, h = bh % HH;
    int qb = blockIdx.x;
    int sp = blockIdx.z;
    int tid = threadIdx.x;
    int qi  = tid >> 1;
    int par = tid & 1;
    int warp = tid >> 5;
    int q    = qb * 64 + qi;
    int tok  = b * TT + q;
    int qwmax = qb * 64 + warp * 16 + 15;

    float4 a4[8];
    #pragma unroll
    for (int i = 0; i < 8; i++) a4[i] = make_float4(0.f, 0.f, 0.f, 0.f);
    float mmax = -1e30f, lsum = 0.f;

    if (sp <= qb) {
        float4 q4[8];
        const float4* qp = (const float4*)(qkv + (size_t)tok * DQKV + h * HD);
        #pragma unroll
        for (int t = 0; t < 8; t++) {
            q4[t] = qp[2*t + par];
            q4[t].x *= 0.125f; q4[t].y *= 0.125f; q4[t].z *= 0.125f; q4[t].w *= 0.125f;
        }

        for (int kt = sp; kt <= qb; kt += NSPLIT) {
            const float* kb = qkv + (size_t)(b*TT + kt*64) * DQKV + DD + h*HD;
            const float* vb = kb + DD;
            __syncthreads();
            #pragma unroll
            for (int c = 0; c < 8; c++) {
                int f = c * 128 + tid;
                int row = f >> 4, col = f & 15;
                Ks[f] = *(const float4*)(kb + (size_t)row * DQKV + col * 4);
                Vs[f] = *(const float4*)(vb + (size_t)row * DQKV + col * 4);
            }
            __syncthreads();

            int jm = qwmax - kt*64 + 1;
            if (jm > 64) jm = 64;
            for (int j = 0; j < jm; j++) {
                const float4* kr = &Ks[j * 16];
                float sA, sB, sC, sD;
                sA  = dot4(q4[0], kr[0 + par]);
                sB  = dot4(q4[1], kr[2 + par]);
                sC  = dot4(q4[2], kr[4 + par]);
                sD  = dot4(q4[3], kr[6 + par]);
                sA += dot4(q4[4], kr[8 + par]);
                sB += dot4(q4[5], kr[10 + par]);
                sC += dot4(q4[6], kr[12 + par]);
                sD += dot4(q4[7], kr[14 + par]);
                float s = (sA + sB) + (sC + sD);
                s += __shfl_xor_sync(0xffffffffu, s, 1);

                int rel = kt*64 + j;
                bool ok = (rel <= q);
                float p;
                if (ok && s > mmax) {
                    float corr = __expf(mmax - s);
                    #pragma unroll
                    for (int i = 0; i < 8; i++) {
                        a4[i].x *= corr; a4[i].y *= corr;
                        a4[i].z *= corr; a4[i].w *= corr;
                    }
                    lsum *= corr; mmax = s; p = 1.f;
                } else {
                    p = ok ? __expf(s - mmax) : 0.f;
                }
                lsum += p;

                const float4* vr = &Vs[j * 16];
                #pragma unroll
                for (int t = 0; t < 8; t++) {
                    float4 vv = vr[2*t + par];
                    a4[t].x = fmaf(p, vv.x, a4[t].x);
                    a4[t].y = fmaf(p, vv.y, a4[t].y);
                    a4[t].z = fmaf(p, vv.z, a4[t].z);
                    a4[t].w = fmaf(p, vv.w, a4[t].w);
                }
            }
        }
    }

    size_t ab = ((size_t)sp * NTOK + tok) * DD + h * HD;
    #pragma unroll
    for (int t = 0; t < 8; t++)
        *(float4*)&pacc[ab + (2*t + par) * 4] = a4[t];
    if (par == 0) {
        size_t mi = ((size_t)sp * NTOK + tok) * HH + h;
        pm[mi] = mmax;
        pl[mi] = lsum;
    }
}

// Merge NSPLIT partials -> bf16 hi/lo attention output.
__global__ __launch_bounds__(64)
void attn_merge(const float* __restrict__ pacc, const float* __restrict__ pm,
                const float* __restrict__ pl,
                __nv_bfloat16* __restrict__ oh, __nv_bfloat16* __restrict__ ol) {
    int tokh = blockIdx.x;
    int tok = tokh / HH, h = tokh % HH;
    int d = threadIdx.x;

    float m[NSPLIT], l[NSPLIT];
    float M = -1e30f;
    #pragma unroll
    for (int s = 0; s < NSPLIT; s++) {
        size_t mi = ((size_t)s * NTOK + tok) * HH + h;
        m[s] = pm[mi]; l[s] = pl[mi];
        M = fmaxf(M, m[s]);
    }
    float L = 0.f, w[NSPLIT];
    #pragma unroll
    for (int s = 0; s < NSPLIT; s++) {
        w[s] = __expf(m[s] - M);
        L = fmaf(l[s], w[s], L);
    }
    float v = 0.f;
    #pragma unroll
    for (int s = 0; s < NSPLIT; s++) {
        size_t ab = ((size_t)s * NTOK + tok) * DD + h * HD + d;
        v = fmaf(pacc[ab], w[s], v);
    }
    float f = v / L;
    size_t ob = (size_t)tok * DD + h * HD + d;
    __nv_bfloat16 hh = __float2bfloat16(f);
    oh[ob] = hh;
    ol[ob] = __float2bfloat16(f - __bfloat162float(hh));
}

// ---------------- Driver ---------------------------
extern "C" void kernel_launch(void* const* d_in, const int* in_sizes, int n_in,
                              void* d_out, int out_size) {
    (void)in_sizes; (void)n_in; (void)out_size;
    const int*   x       = (const int*)  d_in[0];
    const float* tok_emb = (const float*)d_in[1];
    const float* pos_emb = (const float*)d_in[2];
    const float* qkv_w   = (const float*)d_in[3];
    const float* fc_w    = (const float*)d_in[4];
    const float* fc_b    = (const float*)d_in[5];
    const float* ln1_s   = (const float*)d_in[6];
    const float* ln1_b   = (const float*)d_in[7];
    const float* ln2_s   = (const float*)d_in[8];
    const float* ln2_b   = (const float*)d_in[9];
    const float* ff1_w   = (const float*)d_in[10];
    const float* ff1_b   = (const float*)d_in[11];
    const float* ff2_w   = (const float*)d_in[12];
    const float* ff2_b   = (const float*)d_in[13];
    const float* lnf_s   = (const float*)d_in[14];
    const float* lnf_b   = (const float*)d_in[15];
    const float* out_w   = (const float*)d_in[16];
    const float* out_b   = (const float*)d_in[17];
    float* logits = (float*)d_out;

    cudaFuncSetAttribute(mm_kernel<0>, cudaFuncAttributeMaxDynamicSharedMemorySize, GEMM_SMEM);
    cudaFuncSetAttribute(mm_kernel<1>, cudaFuncAttributeMaxDynamicSharedMemorySize, GEMM_SMEM);
    cudaFuncSetAttribute(mm_kernel<2>, cudaFuncAttributeMaxDynamicSharedMemorySize, GEMM_SMEM);
    cudaFuncSetAttribute(mm_kernel<3>, cudaFuncAttributeMaxDynamicSharedMemorySize, GEMM_SMEM);

    float *h, *qkvb, *pacc, *pmv, *plv;
    __nv_bfloat16 *xh, *xl, *ah, *al, *fh, *fl;
    __nv_bfloat16 *qh, *ql, *fch, *fcl, *f1h, *f1l, *f2h, *f2l, *oh, *ol;
    cudaGetSymbolAddress((void**)&h,    g_h);
    cudaGetSymbolAddress((void**)&qkvb, g_qkv);
    cudaGetSymbolAddress((void**)&pacc, g_pacc);
    cudaGetSymbolAddress((void**)&pmv,  g_pm);
    cudaGetSymbolAddress((void**)&plv,  g_pl);
    cudaGetSymbolAddress((void**)&xh, g_xh);  cudaGetSymbolAddress((void**)&xl, g_xl);
    cudaGetSymbolAddress((void**)&ah, g_ah);  cudaGetSymbolAddress((void**)&al, g_al);
    cudaGetSymbolAddress((void**)&fh, g_fh);  cudaGetSymbolAddress((void**)&fl, g_fl);
    cudaGetSymbolAddress((void**)&qh, w_qkvh); cudaGetSymbolAddress((void**)&ql, w_qkvl);
    cudaGetSymbolAddress((void**)&fch, w_fch); cudaGetSymbolAddress((void**)&fcl, w_fcl);
    cudaGetSymbolAddress((void**)&f1h, w_f1h); cudaGetSymbolAddress((void**)&f1l, w_f1l);
    cudaGetSymbolAddress((void**)&f2h, w_f2h); cudaGetSymbolAddress((void**)&f2l, w_f2l);
    cudaGetSymbolAddress((void**)&oh, w_oh);   cudaGetSymbolAddress((void**)&ol, w_ol);

    cvt_kernel<<<2048, 256>>>(qkv_w, qh, ql, LL*DQKV*DD/4);
    cvt_kernel<<<1024, 256>>>(fc_w,  fch, fcl, LL*DD*DD/4);
    cvt_kernel<<<2048, 256>>>(ff1_w, f1h, f1l, LL*DFF*DD/4);
    cvt_kernel<<<2048, 256>>>(ff2_w, f2h, f2l, LL*DD*DFF/4);
    cvt_kernel<<<4096, 256>>>(out_w, oh, ol, VV*DD/4);

    embed_kernel<<<NTOK, 256>>>(x, tok_emb, pos_emb);

    for (int l = 0; l < LL; l++) {
        const __nv_bfloat16* wqh = qh + (size_t)l * DQKV * DD;
        const __nv_bfloat16* wql = ql + (size_t)l * DQKV * DD;
        const __nv_bfloat16* wph = fch + (size_t)l * DD * DD;
        const __nv_bfloat16* wpl = fcl + (size_t)l * DD * DD;
        const __nv_bfloat16* w1h = f1h + (size_t)l * DFF * DD;
        const __nv_bfloat16* w1l = f1l + (size_t)l * DFF * DD;
        const __nv_bfloat16* w2h = f2h + (size_t)l * DD * DFF;
        const __nv_bfloat16* w2l = f2l + (size_t)l * DD * DFF;

        ln_kernel<<<NTOK, 256>>>(h, ln1_s + (size_t)l*DD, ln1_b + (size_t)l*DD, xh, xl);
        mm_kernel<0><<<dim3(NTOK/128, DQKV/128), 256, GEMM_SMEM>>>(
            xh, xl, wqh, wql, nullptr, qkvb, nullptr, nullptr, DQKV, DD);
        attn_kernel<<<dim3(TT/64, BB*HH, NSPLIT), 128>>>(qkvb, pacc, pmv, plv);
        attn_merge<<<NTOK*HH, 64>>>(pacc, pmv, plv, ah, al);
        mm_kernel<2><<<dim3(NTOK/128, DD/128), 256, GEMM_SMEM>>>(
            ah, al, wph, wpl, fc_b + (size_t)l*DD, h, nullptr, nullptr, DD, DD);
        ln_kernel<<<NTOK, 256>>>(h, ln2_s + (size_t)l*DD, ln2_b + (size_t)l*DD, xh, xl);
        mm_kernel<3><<<dim3(NTOK/128, DFF/128), 256, GEMM_SMEM>>>(
            xh, xl, w1h, w1l, ff1_b + (size_t)l*DFF, nullptr, fh, fl, DFF, DD);
        mm_kernel<2><<<dim3(NTOK/128, DD/128), 256, GEMM_SMEM>>>(
            fh, fl, w2h, w2l, ff2_b + (size_t)l*DD, h, nullptr, nullptr, DD, DFF);
    }

    ln_kernel<<<NTOK, 256>>>(h, lnf_s, lnf_b, xh, xl);
    mm_kernel<1><<<dim3(NTOK/128, VV/128), 256, GEMM_SMEM>>>(
        xh, xl, oh, ol, out_b, logits, nullptr, nullptr, VV, DD);
}

// round 13
// speedup vs baseline: 1.1109x; 1.1109x over previous
#include <cuda_runtime.h>
#include <cuda_bf16.h>
#include <math.h>
#include <stdint.h>

// ---------------- Problem constants ----------------
#define BB    4
#define TT    1024
#define NTOK  (BB*TT)
#define DD    768
#define HH    12
#define HD    64
#define LL    6
#define VV    32000
#define DFF   3072
#define DQKV  2304
#define EPS   1e-5f
#define NSPLIT 8

// ---------------- Static device buffers ------------
__device__ float g_h   [NTOK * DD];
__device__ float g_qkv [NTOK * DQKV];
__device__ __nv_bfloat16 g_xh[NTOK*DD],  g_xl[NTOK*DD];
__device__ __nv_bfloat16 g_ah[NTOK*DD],  g_al[NTOK*DD];
__device__ __nv_bfloat16 g_fh[NTOK*DFF], g_fl[NTOK*DFF];
__device__ float g_pacc[(size_t)NSPLIT * NTOK * DD];
__device__ float g_pm  [(size_t)NSPLIT * NTOK * HH];
__device__ float g_pl  [(size_t)NSPLIT * NTOK * HH];
__device__ __nv_bfloat16 w_qkvh[LL*DQKV*DD], w_qkvl[LL*DQKV*DD];
__device__ __nv_bfloat16 w_fch [LL*DD*DD],   w_fcl [LL*DD*DD];
__device__ __nv_bfloat16 w_f1h [LL*DFF*DD],  w_f1l [LL*DFF*DD];
__device__ __nv_bfloat16 w_f2h [LL*DD*DFF],  w_f2l [LL*DD*DFF];
__device__ __nv_bfloat16 w_oh  [VV*DD],      w_ol  [VV*DD];

// ---------------- PTX helpers ----------------------
__device__ __forceinline__ uint32_t smem_to_u32(const void* p) {
    uint32_t a;
    asm("{ .reg .u64 t; cvta.to.shared.u64 t, %1; cvt.u32.u64 %0, t; }"
        : "=r"(a) : "l"(p));
    return a;
}
#define CP_ASYNC16(dst, src) \
    asm volatile("cp.async.cg.shared.global [%0], [%1], 16;" :: "r"(dst), "l"(src))
#define CP_COMMIT asm volatile("cp.async.commit_group;" ::: "memory")
#define CP_WAIT1  asm volatile("cp.async.wait_group 1;" ::: "memory")
#define CP_WAIT0  asm volatile("cp.async.wait_group 0;" ::: "memory")

__device__ __forceinline__ void ldsm4(uint32_t* r, uint32_t addr) {
    asm volatile("ldmatrix.sync.aligned.m8n8.x4.shared.b16 {%0,%1,%2,%3}, [%4];"
        : "=r"(r[0]), "=r"(r[1]), "=r"(r[2]), "=r"(r[3]) : "r"(addr));
}
__device__ __forceinline__ void ldsm2(uint32_t* r, uint32_t addr) {
    asm volatile("ldmatrix.sync.aligned.m8n8.x2.shared.b16 {%0,%1}, [%2];"
        : "=r"(r[0]), "=r"(r[1]) : "r"(addr));
}
__device__ __forceinline__ void mma_bf16(float* d, const uint32_t* a, const uint32_t* b) {
    asm volatile("mma.sync.aligned.m16n8k16.row.col.f32.bf16.bf16.f32 "
        "{%0,%1,%2,%3}, {%4,%5,%6,%7}, {%8,%9}, {%0,%1,%2,%3};"
        : "+f"(d[0]), "+f"(d[1]), "+f"(d[2]), "+f"(d[3])
        : "r"(a[0]), "r"(a[1]), "r"(a[2]), "r"(a[3]), "r"(b[0]), "r"(b[1]));
}

__device__ __forceinline__ float dot4(const float4& a, const float4& b) {
    return fmaf(a.x, b.x, fmaf(a.y, b.y, fmaf(a.z, b.z, a.w * b.w)));
}

// ---------------- Embedding ------------------------
__global__ void embed_kernel(const int* __restrict__ x,
                             const float* __restrict__ tok_emb,
                             const float* __restrict__ pos_emb) {
    int row = blockIdx.x;
    int t   = row % TT;
    int id  = x[row];
    const float* te = tok_emb + (size_t)id * DD;
    const float* pe = pos_emb + (size_t)t  * DD;
    float* out = g_h + (size_t)row * DD;
    for (int i = threadIdx.x; i < DD; i += blockDim.x)
        out[i] = te[i] + pe[i];
}

// ---------------- fp32 -> bf16 hi/lo split ---------
__global__ void cvt_kernel(const float* __restrict__ s,
                           __nv_bfloat16* __restrict__ hi,
                           __nv_bfloat16* __restrict__ lo, int n4) {
    int i = blockIdx.x * blockDim.x + threadIdx.x;
    int stride = gridDim.x * blockDim.x;
    for (; i < n4; i += stride) {
        float4 v = ((const float4*)s)[i];
        __nv_bfloat16 h0 = __float2bfloat16(v.x);
        __nv_bfloat16 h1 = __float2bfloat16(v.y);
        __nv_bfloat16 h2 = __float2bfloat16(v.z);
        __nv_bfloat16 h3 = __float2bfloat16(v.w);
        __nv_bfloat16 l0 = __float2bfloat16(v.x - __bfloat162float(h0));
        __nv_bfloat16 l1 = __float2bfloat16(v.y - __bfloat162float(h1));
        __nv_bfloat16 l2 = __float2bfloat16(v.z - __bfloat162float(h2));
        __nv_bfloat16 l3 = __float2bfloat16(v.w - __bfloat162float(h3));
        __nv_bfloat162* ph = (__nv_bfloat162*)hi + i*2;
        __nv_bfloat162* pl = (__nv_bfloat162*)lo + i*2;
        ph[0] = __nv_bfloat162(h0, h1); ph[1] = __nv_bfloat162(h2, h3);
        pl[0] = __nv_bfloat162(l0, l1); pl[1] = __nv_bfloat162(l2, l3);
    }
}

// ---------------- LayerNorm -> bf16 hi/lo ----------
__device__ __forceinline__ float block_reduce_sum(float v, float* red) {
    int lane = threadIdx.x & 31, wid = threadIdx.x >> 5;
    #pragma unroll
    for (int o = 16; o > 0; o >>= 1) v += __shfl_xor_sync(0xffffffffu, v, o);
    if (lane == 0) red[wid] = v;
    __syncthreads();
    if (wid == 0) {
        float w = (lane < (blockDim.x >> 5)) ? red[lane] : 0.f;
        #pragma unroll
        for (int o = 4; o > 0; o >>= 1) w += __shfl_xor_sync(0xffffffffu, w, o);
        if (lane == 0) red[0] = w;
    }
    __syncthreads();
    float r = red[0];
    __syncthreads();
    return r;
}

__global__ void ln_kernel(const float* __restrict__ xin,
                          const float* __restrict__ sc,
                          const float* __restrict__ bi,
                          __nv_bfloat16* __restrict__ yh,
                          __nv_bfloat16* __restrict__ yl) {
    __shared__ float red[32];
    int row = blockIdx.x;
    const float* xr = xin + (size_t)row * DD;
    float xv[3];
    float s = 0.f;
    #pragma unroll
    for (int i = 0; i < 3; i++) { xv[i] = xr[threadIdx.x + i*256]; s += xv[i]; }
    float mean = block_reduce_sum(s, red) * (1.0f / DD);
    float vs = 0.f;
    #pragma unroll
    for (int i = 0; i < 3; i++) { float d = xv[i] - mean; vs += d * d; }
    float var = block_reduce_sum(vs, red) * (1.0f / DD);
    float rstd = rsqrtf(var + EPS);
    #pragma unroll
    for (int i = 0; i < 3; i++) {
        int c = threadIdx.x + i*256;
        float v = (xv[i] - mean) * rstd * sc[c] + bi[c];
        __nv_bfloat16 h = __float2bfloat16(v);
        yh[(size_t)row*DD + c] = h;
        yl[(size_t)row*DD + c] = __float2bfloat16(v - __bfloat162float(h));
    }
}

// ---------------- epilogue helper ------------------
template<int OP>
__device__ __forceinline__ void epilogue_store(
    float v0, float v1, size_t off, int gcol,
    const float* __restrict__ bias, float* __restrict__ C,
    __nv_bfloat16* __restrict__ Oh, __nv_bfloat16* __restrict__ Ol) {
    if (OP == 0) {
        *(float2*)&C[off] = make_float2(v0, v1);
    } else if (OP == 1) {
        *(float2*)&C[off] = make_float2(v0 + bias[gcol], v1 + bias[gcol+1]);
    } else if (OP == 2) {
        float2 hcur = *(float2*)&C[off];
        *(float2*)&C[off] = make_float2(v0 + bias[gcol]   + hcur.x,
                                        v1 + bias[gcol+1] + hcur.y);
    } else {
        float f0 = fmaxf(v0 + bias[gcol],   0.f);
        float f1 = fmaxf(v1 + bias[gcol+1], 0.f);
        __nv_bfloat16 h0 = __float2bfloat16(f0);
        __nv_bfloat16 h1 = __float2bfloat16(f1);
        *(__nv_bfloat162*)&Oh[off] = __nv_bfloat162(h0, h1);
        __nv_bfloat16 l0 = __float2bfloat16(f0 - __bfloat162float(h0));
        __nv_bfloat16 l1 = __float2bfloat16(f1 - __bfloat162float(h1));
        *(__nv_bfloat162*)&Ol[off] = __nv_bfloat162(l0, l1);
    }
}

// =============== 128x64 HMMA GEMM, KC=64, 2 CTAs/SM (validated) ============
#define KC         64
#define S_AH       0
#define S_AL       16384
#define S_WH       32768
#define S_WL       40960
#define STG_B      49152
#define GEMM_SMEM  (2*STG_B)

template<int OP>
__global__ __launch_bounds__(256, 2)
void mm_kernel(const __nv_bfloat16* __restrict__ Ah, const __nv_bfloat16* __restrict__ Al,
               const __nv_bfloat16* __restrict__ Wh, const __nv_bfloat16* __restrict__ Wl,
               const float* __restrict__ bias, float* __restrict__ C,
               __nv_bfloat16* __restrict__ Oh, __nv_bfloat16* __restrict__ Ol,
               int N, int K) {
    extern __shared__ char smem[];
    const uint32_t sb = smem_to_u32(smem);
    int tid = threadIdx.x, lane = tid & 31, warp = tid >> 5;
    int wm = warp >> 1;
    int wn = warp & 1;
    int bm = blockIdx.x * 128, bn = blockIdx.y * 64;

    float acc[2][4][4];
    #pragma unroll
    for (int i = 0; i < 2; i++)
        #pragma unroll
        for (int j = 0; j < 4; j++)
            #pragma unroll
            for (int k = 0; k < 4; k++) acc[i][j][k] = 0.f;

    int arow = tid >> 1;
    int ac0  = (tid & 1) * 4;
    const __nv_bfloat16* gA_h = Ah + (size_t)(bm + arow) * K + ac0 * 8;
    const __nv_bfloat16* gA_l = Al + (size_t)(bm + arow) * K + ac0 * 8;
    uint32_t asrow = (uint32_t)arow * 128;
    int arsw = arow & 7;
    int wrow = tid >> 2;
    int wc0  = (tid & 3) * 2;
    const __nv_bfloat16* gW_h = Wh + (size_t)(bn + wrow) * K + wc0 * 8;
    const __nv_bfloat16* gW_l = Wl + (size_t)(bn + wrow) * K + wc0 * 8;
    uint32_t wsrow = (uint32_t)wrow * 128;
    int wrsw = wrow & 7;

    int mat = lane >> 3, r8 = lane & 7;
    int a_kh = mat >> 1;
    uint32_t arowb[2]; int aswz[2];
    #pragma unroll
    for (int ti = 0; ti < 2; ti++) {
        int row = wm*32 + ti*16 + (mat & 1)*8 + r8;
        arowb[ti] = (uint32_t)row * 128;
        aswz[ti]  = row & 7;
    }
    int bl15 = lane & 15;
    int b_kh = bl15 >> 3;
    uint32_t browb[4]; int bswz[4];
    #pragma unroll
    for (int ni = 0; ni < 4; ni++) {
        int row = wn*32 + ni*8 + (bl15 & 7);
        browb[ni] = (uint32_t)row * 128;
        bswz[ni]  = row & 7;
    }

    const int nch = K / KC;
    {
        uint32_t st = sb;
        #pragma unroll
        for (int i = 0; i < 4; i++) {
            int c = ac0 + i;
            uint32_t soff = asrow + (uint32_t)((c ^ arsw) << 4);
            CP_ASYNC16(st + S_AH + soff, gA_h + i*8);
            CP_ASYNC16(st + S_AL + soff, gA_l + i*8);
        }
        #pragma unroll
        for (int i = 0; i < 2; i++) {
            int c = wc0 + i;
            uint32_t soff = wsrow + (uint32_t)((c ^ wrsw) << 4);
            CP_ASYNC16(st + S_WH + soff, gW_h + i*8);
            CP_ASYNC16(st + S_WL + soff, gW_l + i*8);
        }
        CP_COMMIT;
    }

    for (int ch = 0; ch < nch; ch++) {
        if (ch + 1 < nch) {
            uint32_t st = sb + ((ch + 1) & 1) * STG_B;
            int k0 = (ch + 1) * KC;
            #pragma unroll
            for (int i = 0; i < 4; i++) {
                int c = ac0 + i;
                uint32_t soff = asrow + (uint32_t)((c ^ arsw) << 4);
                CP_ASYNC16(st + S_AH + soff, gA_h + k0 + i*8);
                CP_ASYNC16(st + S_AL + soff, gA_l + k0 + i*8);
            }
            #pragma unroll
            for (int i = 0; i < 2; i++) {
                int c = wc0 + i;
                uint32_t soff = wsrow + (uint32_t)((c ^ wrsw) << 4);
                CP_ASYNC16(st + S_WH + soff, gW_h + k0 + i*8);
                CP_ASYNC16(st + S_WL + soff, gW_l + k0 + i*8);
            }
            CP_COMMIT;
            CP_WAIT1;
        } else {
            CP_WAIT0;
        }
        __syncthreads();

        uint32_t stg = sb + (ch & 1) * STG_B;
        #pragma unroll
        for (int ks = 0; ks < 4; ks++) {
            uint32_t ahf[2][4], alf[2][4];
            #pragma unroll
            for (int ti = 0; ti < 2; ti++) {
                uint32_t off = arowb[ti] + (uint32_t)((((ks << 1) | a_kh) ^ aswz[ti]) << 4);
                ldsm4(ahf[ti], stg + S_AH + off);
                ldsm4(alf[ti], stg + S_AL + off);
            }
            uint32_t bhf[4][2], blf[4][2];
            #pragma unroll
            for (int ni = 0; ni < 4; ni++) {
                uint32_t off = browb[ni] + (uint32_t)((((ks << 1) | b_kh) ^ bswz[ni]) << 4);
                ldsm2(bhf[ni], stg + S_WH + off);
                ldsm2(blf[ni], stg + S_WL + off);
            }
            #pragma unroll
            for (int ti = 0; ti < 2; ti++)
                #pragma unroll
                for (int ni = 0; ni < 4; ni++) {
                    mma_bf16(acc[ti][ni], ahf[ti], bhf[ni]);
                    mma_bf16(acc[ti][ni], ahf[ti], blf[ni]);
                    mma_bf16(acc[ti][ni], alf[ti], bhf[ni]);
                }
        }
        __syncthreads();
    }

    int lr = lane >> 2, lc = (lane & 3) * 2;
    #pragma unroll
    for (int ti = 0; ti < 2; ti++)
        #pragma unroll
        for (int ni = 0; ni < 4; ni++) {
            int grow = bm + wm*32 + ti*16 + lr;
            int gcol = bn + wn*32 + ni*8 + lc;
            #pragma unroll
            for (int half = 0; half < 2; half++) {
                int r = grow + half*8;
                epilogue_store<OP>(acc[ti][ni][half*2], acc[ti][ni][half*2+1],
                                   (size_t)r * N + gcol, gcol, bias, C, Oh, Ol);
            }
        }
}

// =============== 128x96 HMMA GEMM, KC=64, 2 CTAs/SM ========================
// Stage: Ah 16KB | Al 16KB | Wh 12KB | Wl 12KB = 56KB; 2 stages = 112KB.
// 8 warps as 4(M) x 2(N); warp tile 32x48. Same 128B-row XOR swizzle.
#define N96        96
#define M_AH       0
#define M_AL       16384
#define M_WH       32768
#define M_WL       45056
#define STG96_B    57344
#define GEMM96_SMEM (2*STG96_B)

template<int OP>
__global__ __launch_bounds__(256, 2)
void mm96(const __nv_bfloat16* __restrict__ Ah, const __nv_bfloat16* __restrict__ Al,
          const __nv_bfloat16* __restrict__ Wh, const __nv_bfloat16* __restrict__ Wl,
          const float* __restrict__ bias, float* __restrict__ C,
          __nv_bfloat16* __restrict__ Oh, __nv_bfloat16* __restrict__ Ol,
          int N, int K) {
    extern __shared__ char smem[];
    const uint32_t sb = smem_to_u32(smem);
    int tid = threadIdx.x, lane = tid & 31, warp = tid >> 5;
    int wm = warp >> 1;              // 0..3 -> 32 rows
    int wn = warp & 1;               // 0..1 -> 48 cols
    int bm = blockIdx.x * 128, bn = blockIdx.y * N96;

    float acc[2][6][4];
    #pragma unroll
    for (int i = 0; i < 2; i++)
        #pragma unroll
        for (int j = 0; j < 6; j++)
            #pragma unroll
            for (int k = 0; k < 4; k++) acc[i][j][k] = 0.f;

    // A loader: row = tid/2, 4 chunks (validated mapping)
    int arow = tid >> 1;
    int ac0  = (tid & 1) * 4;
    const __nv_bfloat16* gA_h = Ah + (size_t)(bm + arow) * K + ac0 * 8;
    const __nv_bfloat16* gA_l = Al + (size_t)(bm + arow) * K + ac0 * 8;
    uint32_t asrow = (uint32_t)arow * 128;
    int arsw = arow & 7;
    // W loader: 96 rows x 8 chunks = 768 16B units; 3 units per thread
    const __nv_bfloat16* gWh0 = Wh + (size_t)bn * K;
    const __nv_bfloat16* gWl0 = Wl + (size_t)bn * K;

    // ldmatrix lane constants
    int mat = lane >> 3, r8 = lane & 7;
    int a_kh = mat >> 1;
    uint32_t arowb[2]; int aswz[2];
    #pragma unroll
    for (int ti = 0; ti < 2; ti++) {
        int row = wm*32 + ti*16 + (mat & 1)*8 + r8;
        arowb[ti] = (uint32_t)row * 128;
        aswz[ti]  = row & 7;
    }
    int bl15 = lane & 15;
    int b_kh = bl15 >> 3;
    uint32_t browb[6]; int bswz[6];
    #pragma unroll
    for (int ni = 0; ni < 6; ni++) {
        int row = wn*48 + ni*8 + (bl15 & 7);
        browb[ni] = (uint32_t)row * 128;
        bswz[ni]  = row & 7;
    }

    const int nch = K / KC;
    {
        uint32_t st = sb;
        #pragma unroll
        for (int i = 0; i < 4; i++) {
            int c = ac0 + i;
            uint32_t soff = asrow + (uint32_t)((c ^ arsw) << 4);
            CP_ASYNC16(st + M_AH + soff, gA_h + i*8);
            CP_ASYNC16(st + M_AL + soff, gA_l + i*8);
        }
        #pragma unroll
        for (int i = 0; i < 3; i++) {
            int u = tid + i*256;
            int row = u >> 3, c = u & 7;
            uint32_t soff = (uint32_t)row * 128 + (uint32_t)((c ^ (row & 7)) << 4);
            size_t go = (size_t)row * K + c * 8;
            CP_ASYNC16(st + M_WH + soff, gWh0 + go);
            CP_ASYNC16(st + M_WL + soff, gWl0 + go);
        }
        CP_COMMIT;
    }

    for (int ch = 0; ch < nch; ch++) {
        if (ch + 1 < nch) {
            uint32_t st = sb + ((ch + 1) & 1) * STG96_B;
            int k0 = (ch + 1) * KC;
            #pragma unroll
            for (int i = 0; i < 4; i++) {
                int c = ac0 + i;
                uint32_t soff = asrow + (uint32_t)((c ^ arsw) << 4);
                CP_ASYNC16(st + M_AH + soff, gA_h + k0 + i*8);
                CP_ASYNC16(st + M_AL + soff, gA_l + k0 + i*8);
            }
            #pragma unroll
            for (int i = 0; i < 3; i++) {
                int u = tid + i*256;
                int row = u >> 3, c = u & 7;
                uint32_t soff = (uint32_t)row * 128 + (uint32_t)((c ^ (row & 7)) << 4);
                size_t go = (size_t)row * K + k0 + c * 8;
                CP_ASYNC16(st + M_WH + soff, gWh0 + go);
                CP_ASYNC16(st + M_WL + soff, gWl0 + go);
            }
            CP_COMMIT;
            CP_WAIT1;
        } else {
            CP_WAIT0;
        }
        __syncthreads();

        uint32_t stg = sb + (ch & 1) * STG96_B;
        #pragma unroll
        for (int ks = 0; ks < 4; ks++) {
            uint32_t ahf[2][4], alf[2][4];
            #pragma unroll
            for (int ti = 0; ti < 2; ti++) {
                uint32_t off = arowb[ti] + (uint32_t)((((ks << 1) | a_kh) ^ aswz[ti]) << 4);
                ldsm4(ahf[ti], stg + M_AH + off);
                ldsm4(alf[ti], stg + M_AL + off);
            }
            uint32_t bhf[6][2], blf[6][2];
            #pragma unroll
            for (int ni = 0; ni < 6; ni++) {
                uint32_t off = browb[ni] + (uint32_t)((((ks << 1) | b_kh) ^ bswz[ni]) << 4);
                ldsm2(bhf[ni], stg + M_WH + off);
                ldsm2(blf[ni], stg + M_WL + off);
            }
            #pragma unroll
            for (int ti = 0; ti < 2; ti++)
                #pragma unroll
                for (int ni = 0; ni < 6; ni++) {
                    mma_bf16(acc[ti][ni], ahf[ti], bhf[ni]);
                    mma_bf16(acc[ti][ni], ahf[ti], blf[ni]);
                    mma_bf16(acc[ti][ni], alf[ti], bhf[ni]);
                }
        }
        __syncthreads();
    }

    int lr = lane >> 2, lc = (lane & 3) * 2;
    #pragma unroll
    for (int ti = 0; ti < 2; ti++)
        #pragma unroll
        for (int ni = 0; ni < 6; ni++) {
            int grow = bm + wm*32 + ti*16 + lr;
            int gcol = bn + wn*48 + ni*8 + lc;
            #pragma unroll
            for (int half = 0; half < 2; half++) {
                int r = grow + half*8;
                epilogue_store<OP>(acc[ti][ni][half*2], acc[ti][ni][half*2+1],
                                   (size_t)r * N + gcol, gcol, bias, C, Oh, Ol);
            }
        }
}

// =============== Causal attention: pair-split + KV-split (S=8, validated) ==
__global__ __launch_bounds__(128)
void attn_kernel(const float* __restrict__ qkv,
                 float* __restrict__ pacc, float* __restrict__ pm,
                 float* __restrict__ pl) {
    __shared__ float4 Ks[1024];
    __shared__ float4 Vs[1024];

    int bh = blockIdx.y;
    int b  = bh / HH, h = bh % HH;
    int qb = blockIdx.x;
    int sp = blockIdx.z;
    int tid = threadIdx.x;
    int qi  = tid >> 1;
    int par = tid & 1;
    int warp = tid >> 5;
    int q    = qb * 64 + qi;
    int tok  = b * TT + q;
    int qwmax = qb * 64 + warp * 16 + 15;

    float4 a4[8];
    #pragma unroll
    for (int i = 0; i < 8; i++) a4[i] = make_float4(0.f, 0.f, 0.f, 0.f);
    float mmax = -1e30f, lsum = 0.f;

    if (sp <= qb) {
        float4 q4[8];
        const float4* qp = (const float4*)(qkv + (size_t)tok * DQKV + h * HD);
        #pragma unroll
        for (int t = 0; t < 8; t++) {
            q4[t] = qp[2*t + par];
            q4[t].x *= 0.125f; q4[t].y *= 0.125f; q4[t].z *= 0.125f; q4[t].w *= 0.125f;
        }

        for (int kt = sp; kt <= qb; kt += NSPLIT) {
            const float* kb = qkv + (size_t)(b*TT + kt*64) * DQKV + DD + h*HD;
            const float* vb = kb + DD;
            __syncthreads();
            #pragma unroll
            for (int c = 0; c < 8; c++) {
                int f = c * 128 + tid;
                int row = f >> 4, col = f & 15;
                Ks[f] = *(const float4*)(kb + (size_t)row * DQKV + col * 4);
                Vs[f] = *(const float4*)(vb + (size_t)row * DQKV + col * 4);
            }
            __syncthreads();

            int jm = qwmax - kt*64 + 1;
            if (jm > 64) jm = 64;
            for (int j = 0; j < jm; j++) {
                const float4* kr = &Ks[j * 16];
                float sA, sB, sC, sD;
                sA  = dot4(q4[0], kr[0 + par]);
                sB  = dot4(q4[1], kr[2 + par]);
                sC  = dot4(q4[2], kr[4 + par]);
                sD  = dot4(q4[3], kr[6 + par]);
                sA += dot4(q4[4], kr[8 + par]);
                sB += dot4(q4[5], kr[10 + par]);
                sC += dot4(q4[6], kr[12 + par]);
                sD += dot4(q4[7], kr[14 + par]);
                float s = (sA + sB) + (sC + sD);
                s += __shfl_xor_sync(0xffffffffu, s, 1);

                int rel = kt*64 + j;
                bool ok = (rel <= q);
                float p;
                if (ok && s > mmax) {
                    float corr = __expf(mmax - s);
                    #pragma unroll
                    for (int i = 0; i < 8; i++) {
                        a4[i].x *= corr; a4[i].y *= corr;
                        a4[i].z *= corr; a4[i].w *= corr;
                    }
                    lsum *= corr; mmax = s; p = 1.f;
                } else {
                    p = ok ? __expf(s - mmax) : 0.f;
                }
                lsum += p;

                const float4* vr = &Vs[j * 16];
                #pragma unroll
                for (int t = 0; t < 8; t++) {
                    float4 vv = vr[2*t + par];
                    a4[t].x = fmaf(p, vv.x, a4[t].x);
                    a4[t].y = fmaf(p, vv.y, a4[t].y);
                    a4[t].z = fmaf(p, vv.z, a4[t].z);
                    a4[t].w = fmaf(p, vv.w, a4[t].w);
                }
            }
        }
    }

    size_t ab = ((size_t)sp * NTOK + tok) * DD + h * HD;
    #pragma unroll
    for (int t = 0; t < 8; t++)
        *(float4*)&pacc[ab + (2*t + par) * 4] = a4[t];
    if (par == 0) {
        size_t mi = ((size_t)sp * NTOK + tok) * HH + h;
        pm[mi] = mmax;
        pl[mi] = lsum;
    }
}

// Merge NSPLIT partials -> bf16 hi/lo attention output.
__global__ __launch_bounds__(64)
void attn_merge(const float* __restrict__ pacc, const float* __restrict__ pm,
                const float* __restrict__ pl,
                __nv_bfloat16* __restrict__ oh, __nv_bfloat16* __restrict__ ol) {
    int tokh = blockIdx.x;
    int tok = tokh / HH, h = tokh % HH;
    int d = threadIdx.x;

    float m[NSPLIT], l[NSPLIT];
    float M = -1e30f;
    #pragma unroll
    for (int s = 0; s < NSPLIT; s++) {
        size_t mi = ((size_t)s * NTOK + tok) * HH + h;
        m[s] = pm[mi]; l[s] = pl[mi];
        M = fmaxf(M, m[s]);
    }
    float L = 0.f, w[NSPLIT];
    #pragma unroll
    for (int s = 0; s < NSPLIT; s++) {
        w[s] = __expf(m[s] - M);
        L = fmaf(l[s], w[s], L);
    }
    float v = 0.f;
    #pragma unroll
    for (int s = 0; s < NSPLIT; s++) {
        size_t ab = ((size_t)s * NTOK + tok) * DD + h * HD + d;
        v = fmaf(pacc[ab], w[s], v);
    }
    float f = v / L;
    size_t ob = (size_t)tok * DD + h * HD + d;
    __nv_bfloat16 hh = __float2bfloat16(f);
    oh[ob] = hh;
    ol[ob] = __float2bfloat16(f - __bfloat162float(hh));
}

// ---------------- Driver ---------------------------
extern "C" void kernel_launch(void* const* d_in, const int* in_sizes, int n_in,
                              void* d_out, int out_size) {
    (void)in_sizes; (void)n_in; (void)out_size;
    const int*   x       = (const int*)  d_in[0];
    const float* tok_emb = (const float*)d_in[1];
    const float* pos_emb = (const float*)d_in[2];
    const float* qkv_w   = (const float*)d_in[3];
    const float* fc_w    = (const float*)d_in[4];
    const float* fc_b    = (const float*)d_in[5];
    const float* ln1_s   = (const float*)d_in[6];
    const float* ln1_b   = (const float*)d_in[7];
    const float* ln2_s   = (const float*)d_in[8];
    const float* ln2_b   = (const float*)d_in[9];
    const float* ff1_w   = (const float*)d_in[10];
    const float* ff1_b   = (const float*)d_in[11];
    const float* ff2_w   = (const float*)d_in[12];
    const float* ff2_b   = (const float*)d_in[13];
    const float* lnf_s   = (const float*)d_in[14];
    const float* lnf_b   = (const float*)d_in[15];
    const float* out_w   = (const float*)d_in[16];
    const float* out_b   = (const float*)d_in[17];
    float* logits = (float*)d_out;

    cudaFuncSetAttribute(mm_kernel<1>, cudaFuncAttributeMaxDynamicSharedMemorySize, GEMM_SMEM);
    cudaFuncSetAttribute(mm96<0>, cudaFuncAttributeMaxDynamicSharedMemorySize, GEMM96_SMEM);
    cudaFuncSetAttribute(mm96<2>, cudaFuncAttributeMaxDynamicSharedMemorySize, GEMM96_SMEM);
    cudaFuncSetAttribute(mm96<3>, cudaFuncAttributeMaxDynamicSharedMemorySize, GEMM96_SMEM);

    float *h, *qkvb, *pacc, *pmv, *plv;
    __nv_bfloat16 *xh, *xl, *ah, *al, *fh, *fl;
    __nv_bfloat16 *qh, *ql, *fch, *fcl, *f1h, *f1l, *f2h, *f2l, *oh, *ol;
    cudaGetSymbolAddress((void**)&h,    g_h);
    cudaGetSymbolAddress((void**)&qkvb, g_qkv);
    cudaGetSymbolAddress((void**)&pacc, g_pacc);
    cudaGetSymbolAddress((void**)&pmv,  g_pm);
    cudaGetSymbolAddress((void**)&plv,  g_pl);
    cudaGetSymbolAddress((void**)&xh, g_xh);  cudaGetSymbolAddress((void**)&xl, g_xl);
    cudaGetSymbolAddress((void**)&ah, g_ah);  cudaGetSymbolAddress((void**)&al, g_al);
    cudaGetSymbolAddress((void**)&fh, g_fh);  cudaGetSymbolAddress((void**)&fl, g_fl);
    cudaGetSymbolAddress((void**)&qh, w_qkvh); cudaGetSymbolAddress((void**)&ql, w_qkvl);
    cudaGetSymbolAddress((void**)&fch, w_fch); cudaGetSymbolAddress((void**)&fcl, w_fcl);
    cudaGetSymbolAddress((void**)&f1h, w_f1h); cudaGetSymbolAddress((void**)&f1l, w_f1l);
    cudaGetSymbolAddress((void**)&f2h, w_f2h); cudaGetSymbolAddress((void**)&f2l, w_f2l);
    cudaGetSymbolAddress((void**)&oh, w_oh);   cudaGetSymbolAddress((void**)&ol, w_ol);

    cvt_kernel<<<2048, 256>>>(qkv_w, qh, ql, LL*DQKV*DD/4);
    cvt_kernel<<<1024, 256>>>(fc_w,  fch, fcl, LL*DD*DD/4);
    cvt_kernel<<<2048, 256>>>(ff1_w, f1h, f1l, LL*DFF*DD/4);
    cvt_kernel<<<2048, 256>>>(ff2_w, f2h, f2l, LL*DD*DFF/4);
    cvt_kernel<<<4096, 256>>>(out_w, oh, ol, VV*DD/4);

    embed_kernel<<<NTOK, 256>>>(x, tok_emb, pos_emb);

    for (int l = 0; l < LL; l++) {
        const __nv_bfloat16* wqh = qh + (size_t)l * DQKV * DD;
        const __nv_bfloat16* wql = ql + (size_t)l * DQKV * DD;
        const __nv_bfloat16* wph = fch + (size_t)l * DD * DD;
        const __nv_bfloat16* wpl = fcl + (size_t)l * DD * DD;
        const __nv_bfloat16* w1h = f1h + (size_t)l * DFF * DD;
        const __nv_bfloat16* w1l = f1l + (size_t)l * DFF * DD;
        const __nv_bfloat16* w2h = f2h + (size_t)l * DD * DFF;
        const __nv_bfloat16* w2l = f2l + (size_t)l * DD * DFF;

        ln_kernel<<<NTOK, 256>>>(h, ln1_s + (size_t)l*DD, ln1_b + (size_t)l*DD, xh, xl);
        mm96<0><<<dim3(NTOK/128, DQKV/N96), 256, GEMM96_SMEM>>>(
            xh, xl, wqh, wql, nullptr, qkvb, nullptr, nullptr, DQKV, DD);
        attn_kernel<<<dim3(TT/64, BB*HH, NSPLIT), 128>>>(qkvb, pacc, pmv, plv);
        attn_merge<<<NTOK*HH, 64>>>(pacc, pmv, plv, ah, al);
        mm96<2><<<dim3(NTOK/128, DD/N96), 256, GEMM96_SMEM>>>(
            ah, al, wph, wpl, fc_b + (size_t)l*DD, h, nullptr, nullptr, DD, DD);
        ln_kernel<<<NTOK, 256>>>(h, ln2_s + (size_t)l*DD, ln2_b + (size_t)l*DD, xh, xl);
        mm96<3><<<dim3(NTOK/128, DFF/N96), 256, GEMM96_SMEM>>>(
            xh, xl, w1h, w1l, ff1_b + (size_t)l*DFF, nullptr, fh, fl, DFF, DD);
        mm96<2><<<dim3(NTOK/128, DD/N96), 256, GEMM96_SMEM>>>(
            fh, fl, w2h, w2l, ff2_b + (size_t)l*DD, h, nullptr, nullptr, DD, DFF);
    }

    ln_kernel<<<NTOK, 256>>>(h, lnf_s, lnf_b, xh, xl);
    mm_kernel<1><<<dim3(NTOK/128, VV/64), 256, GEMM_SMEM>>>(
        xh, xl, oh, ol, out_b, logits, nullptr, nullptr, VV, DD);
}

// round 14
// speedup vs baseline: 1.1475x; 1.0329x over previous
#include <cuda_runtime.h>
#include <cuda_bf16.h>
#include <math.h>
#include <stdint.h>

// ---------------- Problem constants ----------------
#define BB    4
#define TT    1024
#define NTOK  (BB*TT)
#define DD    768
#define HH    12
#define HD    64
#define LL    6
#define VV    32000
#define DFF   3072
#define DQKV  2304
#define EPS   1e-5f
#define NSPLIT 8

// ---------------- Static device buffers ------------
__device__ float g_h   [NTOK * DD];
__device__ float g_qkv [NTOK * DQKV];
__device__ __nv_bfloat16 g_xh[NTOK*DD],  g_xl[NTOK*DD];
__device__ __nv_bfloat16 g_ah[NTOK*DD],  g_al[NTOK*DD];
__device__ __nv_bfloat16 g_fh[NTOK*DFF], g_fl[NTOK*DFF];
__device__ float g_pacc[(size_t)NSPLIT * NTOK * DD];
__device__ float g_pm  [(size_t)NSPLIT * NTOK * HH];
__device__ float g_pl  [(size_t)NSPLIT * NTOK * HH];
__device__ __nv_bfloat16 w_qkvh[LL*DQKV*DD], w_qkvl[LL*DQKV*DD];
__device__ __nv_bfloat16 w_fch [LL*DD*DD],   w_fcl [LL*DD*DD];
__device__ __nv_bfloat16 w_f1h [LL*DFF*DD],  w_f1l [LL*DFF*DD];
__device__ __nv_bfloat16 w_f2h [LL*DD*DFF],  w_f2l [LL*DD*DFF];
__device__ __nv_bfloat16 w_oh  [VV*DD],      w_ol  [VV*DD];

// ---------------- PTX helpers ----------------------
__device__ __forceinline__ uint32_t smem_to_u32(const void* p) {
    uint32_t a;
    asm("{ .reg .u64 t; cvta.to.shared.u64 t, %1; cvt.u32.u64 %0, t; }"
        : "=r"(a) : "l"(p));
    return a;
}
#define CP_ASYNC16(dst, src) \
    asm volatile("cp.async.cg.shared.global [%0], [%1], 16;" :: "r"(dst), "l"(src))
#define CP_COMMIT asm volatile("cp.async.commit_group;" ::: "memory")
#define CP_WAIT1  asm volatile("cp.async.wait_group 1;" ::: "memory")
#define CP_WAIT0  asm volatile("cp.async.wait_group 0;" ::: "memory")

__device__ __forceinline__ void ldsm4(uint32_t* r, uint32_t addr) {
    asm volatile("ldmatrix.sync.aligned.m8n8.x4.shared.b16 {%0,%1,%2,%3}, [%4];"
        : "=r"(r[0]), "=r"(r[1]), "=r"(r[2]), "=r"(r[3]) : "r"(addr));
}
__device__ __forceinline__ void ldsm2(uint32_t* r, uint32_t addr) {
    asm volatile("ldmatrix.sync.aligned.m8n8.x2.shared.b16 {%0,%1}, [%2];"
        : "=r"(r[0]), "=r"(r[1]) : "r"(addr));
}
__device__ __forceinline__ void mma_bf16(float* d, const uint32_t* a, const uint32_t* b) {
    asm volatile("mma.sync.aligned.m16n8k16.row.col.f32.bf16.bf16.f32 "
        "{%0,%1,%2,%3}, {%4,%5,%6,%7}, {%8,%9}, {%0,%1,%2,%3};"
        : "+f"(d[0]), "+f"(d[1]), "+f"(d[2]), "+f"(d[3])
        : "r"(a[0]), "r"(a[1]), "r"(a[2]), "r"(a[3]), "r"(b[0]), "r"(b[1]));
}

__device__ __forceinline__ float dot4(const float4& a, const float4& b) {
    return fmaf(a.x, b.x, fmaf(a.y, b.y, fmaf(a.z, b.z, a.w * b.w)));
}

// ---------------- Embedding ------------------------
__global__ void embed_kernel(const int* __restrict__ x,
                             const float* __restrict__ tok_emb,
                             const float* __restrict__ pos_emb) {
    int row = blockIdx.x;
    int t   = row % TT;
    int id  = x[row];
    const float* te = tok_emb + (size_t)id * DD;
    const float* pe = pos_emb + (size_t)t  * DD;
    float* out = g_h + (size_t)row * DD;
    for (int i = threadIdx.x; i < DD; i += blockDim.x)
        out[i] = te[i] + pe[i];
}

// ---------------- fp32 -> bf16 hi/lo split ---------
__global__ void cvt_kernel(const float* __restrict__ s,
                           __nv_bfloat16* __restrict__ hi,
                           __nv_bfloat16* __restrict__ lo, int n4) {
    int i = blockIdx.x * blockDim.x + threadIdx.x;
    int stride = gridDim.x * blockDim.x;
    for (; i < n4; i += stride) {
        float4 v = ((const float4*)s)[i];
        __nv_bfloat16 h0 = __float2bfloat16(v.x);
        __nv_bfloat16 h1 = __float2bfloat16(v.y);
        __nv_bfloat16 h2 = __float2bfloat16(v.z);
        __nv_bfloat16 h3 = __float2bfloat16(v.w);
        __nv_bfloat16 l0 = __float2bfloat16(v.x - __bfloat162float(h0));
        __nv_bfloat16 l1 = __float2bfloat16(v.y - __bfloat162float(h1));
        __nv_bfloat16 l2 = __float2bfloat16(v.z - __bfloat162float(h2));
        __nv_bfloat16 l3 = __float2bfloat16(v.w - __bfloat162float(h3));
        __nv_bfloat162* ph = (__nv_bfloat162*)hi + i*2;
        __nv_bfloat162* pl = (__nv_bfloat162*)lo + i*2;
        ph[0] = __nv_bfloat162(h0, h1); ph[1] = __nv_bfloat162(h2, h3);
        pl[0] = __nv_bfloat162(l0, l1); pl[1] = __nv_bfloat162(l2, l3);
    }
}

// ---------------- LayerNorm -> bf16 hi/lo ----------
__device__ __forceinline__ float block_reduce_sum(float v, float* red) {
    int lane = threadIdx.x & 31, wid = threadIdx.x >> 5;
    #pragma unroll
    for (int o = 16; o > 0; o >>= 1) v += __shfl_xor_sync(0xffffffffu, v, o);
    if (lane == 0) red[wid] = v;
    __syncthreads();
    if (wid == 0) {
        float w = (lane < (blockDim.x >> 5)) ? red[lane] : 0.f;
        #pragma unroll
        for (int o = 4; o > 0; o >>= 1) w += __shfl_xor_sync(0xffffffffu, w, o);
        if (lane == 0) red[0] = w;
    }
    __syncthreads();
    float r = red[0];
    __syncthreads();
    return r;
}

__global__ void ln_kernel(const float* __restrict__ xin,
                          const float* __restrict__ sc,
                          const float* __restrict__ bi,
                          __nv_bfloat16* __restrict__ yh,
                          __nv_bfloat16* __restrict__ yl) {
    __shared__ float red[32];
    int row = blockIdx.x;
    const float* xr = xin + (size_t)row * DD;
    float xv[3];
    float s = 0.f;
    #pragma unroll
    for (int i = 0; i < 3; i++) { xv[i] = xr[threadIdx.x + i*256]; s += xv[i]; }
    float mean = block_reduce_sum(s, red) * (1.0f / DD);
    float vs = 0.f;
    #pragma unroll
    for (int i = 0; i < 3; i++) { float d = xv[i] - mean; vs += d * d; }
    float var = block_reduce_sum(vs, red) * (1.0f / DD);
    float rstd = rsqrtf(var + EPS);
    #pragma unroll
    for (int i = 0; i < 3; i++) {
        int c = threadIdx.x + i*256;
        float v = (xv[i] - mean) * rstd * sc[c] + bi[c];
        __nv_bfloat16 h = __float2bfloat16(v);
        yh[(size_t)row*DD + c] = h;
        yl[(size_t)row*DD + c] = __float2bfloat16(v - __bfloat162float(h));
    }
}

// ---------------- epilogue helper ------------------
template<int OP>
__device__ __forceinline__ void epilogue_store(
    float v0, float v1, size_t off, int gcol,
    const float* __restrict__ bias, float* __restrict__ C,
    __nv_bfloat16* __restrict__ Oh, __nv_bfloat16* __restrict__ Ol) {
    if (OP == 0) {
        *(float2*)&C[off] = make_float2(v0, v1);
    } else if (OP == 1) {
        *(float2*)&C[off] = make_float2(v0 + bias[gcol], v1 + bias[gcol+1]);
    } else if (OP == 2) {
        float2 hcur = *(float2*)&C[off];
        *(float2*)&C[off] = make_float2(v0 + bias[gcol]   + hcur.x,
                                        v1 + bias[gcol+1] + hcur.y);
    } else {
        float f0 = fmaxf(v0 + bias[gcol],   0.f);
        float f1 = fmaxf(v1 + bias[gcol+1], 0.f);
        __nv_bfloat16 h0 = __float2bfloat16(f0);
        __nv_bfloat16 h1 = __float2bfloat16(f1);
        *(__nv_bfloat162*)&Oh[off] = __nv_bfloat162(h0, h1);
        __nv_bfloat16 l0 = __float2bfloat16(f0 - __bfloat162float(h0));
        __nv_bfloat16 l1 = __float2bfloat16(f1 - __bfloat162float(h1));
        *(__nv_bfloat162*)&Ol[off] = __nv_bfloat162(l0, l1);
    }
}

// =============== 128x64 HMMA GEMM, KC=64, 2 CTAs/SM (validated) ============
#define KC         64
#define S_AH       0
#define S_AL       16384
#define S_WH       32768
#define S_WL       40960
#define STG_B      49152
#define GEMM_SMEM  (2*STG_B)

template<int OP>
__global__ __launch_bounds__(256, 2)
void mm_kernel(const __nv_bfloat16* __restrict__ Ah, const __nv_bfloat16* __restrict__ Al,
               const __nv_bfloat16* __restrict__ Wh, const __nv_bfloat16* __restrict__ Wl,
               const float* __restrict__ bias, float* __restrict__ C,
               __nv_bfloat16* __restrict__ Oh, __nv_bfloat16* __restrict__ Ol,
               int N, int K) {
    extern __shared__ char smem[];
    const uint32_t sb = smem_to_u32(smem);
    int tid = threadIdx.x, lane = tid & 31, warp = tid >> 5;
    int wm = warp >> 1;
    int wn = warp & 1;
    int bm = blockIdx.x * 128, bn = blockIdx.y * 64;

    float acc[2][4][4];
    #pragma unroll
    for (int i = 0; i < 2; i++)
        #pragma unroll
        for (int j = 0; j < 4; j++)
            #pragma unroll
            for (int k = 0; k < 4; k++) acc[i][j][k] = 0.f;

    int arow = tid >> 1;
    int ac0  = (tid & 1) * 4;
    const __nv_bfloat16* gA_h = Ah + (size_t)(bm + arow) * K + ac0 * 8;
    const __nv_bfloat16* gA_l = Al + (size_t)(bm + arow) * K + ac0 * 8;
    uint32_t asrow = (uint32_t)arow * 128;
    int arsw = arow & 7;
    int wrow = tid >> 2;
    int wc0  = (tid & 3) * 2;
    const __nv_bfloat16* gW_h = Wh + (size_t)(bn + wrow) * K + wc0 * 8;
    const __nv_bfloat16* gW_l = Wl + (size_t)(bn + wrow) * K + wc0 * 8;
    uint32_t wsrow = (uint32_t)wrow * 128;
    int wrsw = wrow & 7;

    int mat = lane >> 3, r8 = lane & 7;
    int a_kh = mat >> 1;
    uint32_t arowb[2]; int aswz[2];
    #pragma unroll
    for (int ti = 0; ti < 2; ti++) {
        int row = wm*32 + ti*16 + (mat & 1)*8 + r8;
        arowb[ti] = (uint32_t)row * 128;
        aswz[ti]  = row & 7;
    }
    int bl15 = lane & 15;
    int b_kh = bl15 >> 3;
    uint32_t browb[4]; int bswz[4];
    #pragma unroll
    for (int ni = 0; ni < 4; ni++) {
        int row = wn*32 + ni*8 + (bl15 & 7);
        browb[ni] = (uint32_t)row * 128;
        bswz[ni]  = row & 7;
    }

    const int nch = K / KC;
    {
        uint32_t st = sb;
        #pragma unroll
        for (int i = 0; i < 4; i++) {
            int c = ac0 + i;
            uint32_t soff = asrow + (uint32_t)((c ^ arsw) << 4);
            CP_ASYNC16(st + S_AH + soff, gA_h + i*8);
            CP_ASYNC16(st + S_AL + soff, gA_l + i*8);
        }
        #pragma unroll
        for (int i = 0; i < 2; i++) {
            int c = wc0 + i;
            uint32_t soff = wsrow + (uint32_t)((c ^ wrsw) << 4);
            CP_ASYNC16(st + S_WH + soff, gW_h + i*8);
            CP_ASYNC16(st + S_WL + soff, gW_l + i*8);
        }
        CP_COMMIT;
    }

    for (int ch = 0; ch < nch; ch++) {
        if (ch + 1 < nch) {
            uint32_t st = sb + ((ch + 1) & 1) * STG_B;
            int k0 = (ch + 1) * KC;
            #pragma unroll
            for (int i = 0; i < 4; i++) {
                int c = ac0 + i;
                uint32_t soff = asrow + (uint32_t)((c ^ arsw) << 4);
                CP_ASYNC16(st + S_AH + soff, gA_h + k0 + i*8);
                CP_ASYNC16(st + S_AL + soff, gA_l + k0 + i*8);
            }
            #pragma unroll
            for (int i = 0; i < 2; i++) {
                int c = wc0 + i;
                uint32_t soff = wsrow + (uint32_t)((c ^ wrsw) << 4);
                CP_ASYNC16(st + S_WH + soff, gW_h + k0 + i*8);
                CP_ASYNC16(st + S_WL + soff, gW_l + k0 + i*8);
            }
            CP_COMMIT;
            CP_WAIT1;
        } else {
            CP_WAIT0;
        }
        __syncthreads();

        uint32_t stg = sb + (ch & 1) * STG_B;
        #pragma unroll
        for (int ks = 0; ks < 4; ks++) {
            uint32_t ahf[2][4], alf[2][4];
            #pragma unroll
            for (int ti = 0; ti < 2; ti++) {
                uint32_t off = arowb[ti] + (uint32_t)((((ks << 1) | a_kh) ^ aswz[ti]) << 4);
                ldsm4(ahf[ti], stg + S_AH + off);
                ldsm4(alf[ti], stg + S_AL + off);
            }
            uint32_t bhf[4][2], blf[4][2];
            #pragma unroll
            for (int ni = 0; ni < 4; ni++) {
                uint32_t off = browb[ni] + (uint32_t)((((ks << 1) | b_kh) ^ bswz[ni]) << 4);
                ldsm2(bhf[ni], stg + S_WH + off);
                ldsm2(blf[ni], stg + S_WL + off);
            }
            #pragma unroll
            for (int ti = 0; ti < 2; ti++)
                #pragma unroll
                for (int ni = 0; ni < 4; ni++) {
                    mma_bf16(acc[ti][ni], ahf[ti], bhf[ni]);
                    mma_bf16(acc[ti][ni], ahf[ti], blf[ni]);
                    mma_bf16(acc[ti][ni], alf[ti], bhf[ni]);
                }
        }
        __syncthreads();
    }

    int lr = lane >> 2, lc = (lane & 3) * 2;
    #pragma unroll
    for (int ti = 0; ti < 2; ti++)
        #pragma unroll
        for (int ni = 0; ni < 4; ni++) {
            int grow = bm + wm*32 + ti*16 + lr;
            int gcol = bn + wn*32 + ni*8 + lc;
            #pragma unroll
            for (int half = 0; half < 2; half++) {
                int r = grow + half*8;
                epilogue_store<OP>(acc[ti][ni][half*2], acc[ti][ni][half*2+1],
                                   (size_t)r * N + gcol, gcol, bias, C, Oh, Ol);
            }
        }
}

// =============== 128x96 HMMA GEMM, KC=64, 2 CTAs/SM (validated) ============
#define N96        96
#define M_AH       0
#define M_AL       16384
#define M_WH       32768
#define M_WL       45056
#define STG96_B    57344
#define GEMM96_SMEM (2*STG96_B)

template<int OP>
__global__ __launch_bounds__(256, 2)
void mm96(const __nv_bfloat16* __restrict__ Ah, const __nv_bfloat16* __restrict__ Al,
          const __nv_bfloat16* __restrict__ Wh, const __nv_bfloat16* __restrict__ Wl,
          const float* __restrict__ bias, float* __restrict__ C,
          __nv_bfloat16* __restrict__ Oh, __nv_bfloat16* __restrict__ Ol,
          int N, int K) {
    extern __shared__ char smem[];
    const uint32_t sb = smem_to_u32(smem);
    int tid = threadIdx.x, lane = tid & 31, warp = tid >> 5;
    int wm = warp >> 1;
    int wn = warp & 1;
    int bm = blockIdx.x * 128, bn = blockIdx.y * N96;

    float acc[2][6][4];
    #pragma unroll
    for (int i = 0; i < 2; i++)
        #pragma unroll
        for (int j = 0; j < 6; j++)
            #pragma unroll
            for (int k = 0; k < 4; k++) acc[i][j][k] = 0.f;

    int arow = tid >> 1;
    int ac0  = (tid & 1) * 4;
    const __nv_bfloat16* gA_h = Ah + (size_t)(bm + arow) * K + ac0 * 8;
    const __nv_bfloat16* gA_l = Al + (size_t)(bm + arow) * K + ac0 * 8;
    uint32_t asrow = (uint32_t)arow * 128;
    int arsw = arow & 7;
    const __nv_bfloat16* gWh0 = Wh + (size_t)bn * K;
    const __nv_bfloat16* gWl0 = Wl + (size_t)bn * K;

    int mat = lane >> 3, r8 = lane & 7;
    int a_kh = mat >> 1;
    uint32_t arowb[2]; int aswz[2];
    #pragma unroll
    for (int ti = 0; ti < 2; ti++) {
        int row = wm*32 + ti*16 + (mat & 1)*8 + r8;
        arowb[ti] = (uint32_t)row * 128;
        aswz[ti]  = row & 7;
    }
    int bl15 = lane & 15;
    int b_kh = bl15 >> 3;
    uint32_t browb[6]; int bswz[6];
    #pragma unroll
    for (int ni = 0; ni < 6; ni++) {
        int row = wn*48 + ni*8 + (bl15 & 7);
        browb[ni] = (uint32_t)row * 128;
        bswz[ni]  = row & 7;
    }

    const int nch = K / KC;
    {
        uint32_t st = sb;
        #pragma unroll
        for (int i = 0; i < 4; i++) {
            int c = ac0 + i;
            uint32_t soff = asrow + (uint32_t)((c ^ arsw) << 4);
            CP_ASYNC16(st + M_AH + soff, gA_h + i*8);
            CP_ASYNC16(st + M_AL + soff, gA_l + i*8);
        }
        #pragma unroll
        for (int i = 0; i < 3; i++) {
            int u = tid + i*256;
            int row = u >> 3, c = u & 7;
            uint32_t soff = (uint32_t)row * 128 + (uint32_t)((c ^ (row & 7)) << 4);
            size_t go = (size_t)row * K + c * 8;
            CP_ASYNC16(st + M_WH + soff, gWh0 + go);
            CP_ASYNC16(st + M_WL + soff, gWl0 + go);
        }
        CP_COMMIT;
    }

    for (int ch = 0; ch < nch; ch++) {
        if (ch + 1 < nch) {
            uint32_t st = sb + ((ch + 1) & 1) * STG96_B;
            int k0 = (ch + 1) * KC;
            #pragma unroll
            for (int i = 0; i < 4; i++) {
                int c = ac0 + i;
                uint32_t soff = asrow + (uint32_t)((c ^ arsw) << 4);
                CP_ASYNC16(st + M_AH + soff, gA_h + k0 + i*8);
                CP_ASYNC16(st + M_AL + soff, gA_l + k0 + i*8);
            }
            #pragma unroll
            for (int i = 0; i < 3; i++) {
                int u = tid + i*256;
                int row = u >> 3, c = u & 7;
                uint32_t soff = (uint32_t)row * 128 + (uint32_t)((c ^ (row & 7)) << 4);
                size_t go = (size_t)row * K + k0 + c * 8;
                CP_ASYNC16(st + M_WH + soff, gWh0 + go);
                CP_ASYNC16(st + M_WL + soff, gWl0 + go);
            }
            CP_COMMIT;
            CP_WAIT1;
        } else {
            CP_WAIT0;
        }
        __syncthreads();

        uint32_t stg = sb + (ch & 1) * STG96_B;
        #pragma unroll
        for (int ks = 0; ks < 4; ks++) {
            uint32_t ahf[2][4], alf[2][4];
            #pragma unroll
            for (int ti = 0; ti < 2; ti++) {
                uint32_t off = arowb[ti] + (uint32_t)((((ks << 1) | a_kh) ^ aswz[ti]) << 4);
                ldsm4(ahf[ti], stg + M_AH + off);
                ldsm4(alf[ti], stg + M_AL + off);
            }
            uint32_t bhf[6][2], blf[6][2];
            #pragma unroll
            for (int ni = 0; ni < 6; ni++) {
                uint32_t off = browb[ni] + (uint32_t)((((ks << 1) | b_kh) ^ bswz[ni]) << 4);
                ldsm2(bhf[ni], stg + M_WH + off);
                ldsm2(blf[ni], stg + M_WL + off);
            }
            #pragma unroll
            for (int ti = 0; ti < 2; ti++)
                #pragma unroll
                for (int ni = 0; ni < 6; ni++) {
                    mma_bf16(acc[ti][ni], ahf[ti], bhf[ni]);
                    mma_bf16(acc[ti][ni], ahf[ti], blf[ni]);
                    mma_bf16(acc[ti][ni], alf[ti], bhf[ni]);
                }
        }
        __syncthreads();
    }

    int lr = lane >> 2, lc = (lane & 3) * 2;
    #pragma unroll
    for (int ti = 0; ti < 2; ti++)
        #pragma unroll
        for (int ni = 0; ni < 6; ni++) {
            int grow = bm + wm*32 + ti*16 + lr;
            int gcol = bn + wn*48 + ni*8 + lc;
            #pragma unroll
            for (int half = 0; half < 2; half++) {
                int r = grow + half*8;
                epilogue_store<OP>(acc[ti][ni][half*2], acc[ti][ni][half*2+1],
                                   (size_t)r * N + gcol, gcol, bias, C, Oh, Ol);
            }
        }
}

// =============== Causal attention: pair-split + KV-split (S=8, validated) ==
__global__ __launch_bounds__(128)
void attn_kernel(const float* __restrict__ qkv,
                 float* __restrict__ pacc, float* __restrict__ pm,
                 float* __restrict__ pl) {
    __shared__ float4 Ks[1024];
    __shared__ float4 Vs[1024];

    int bh = blockIdx.y;
    int b  = bh / HH, h = bh % HH;
    int qb = blockIdx.x;
    int sp = blockIdx.z;
    int tid = threadIdx.x;
    int qi  = tid >> 1;
    int par = tid & 1;
    int warp = tid >> 5;
    int q    = qb * 64 + qi;
    int tok  = b * TT + q;
    int qwmax = qb * 64 + warp * 16 + 15;

    float4 a4[8];
    #pragma unroll
    for (int i = 0; i < 8; i++) a4[i] = make_float4(0.f, 0.f, 0.f, 0.f);
    float mmax = -1e30f, lsum = 0.f;

    if (sp <= qb) {
        float4 q4[8];
        const float4* qp = (const float4*)(qkv + (size_t)tok * DQKV + h * HD);
        #pragma unroll
        for (int t = 0; t < 8; t++) {
            q4[t] = qp[2*t + par];
            q4[t].x *= 0.125f; q4[t].y *= 0.125f; q4[t].z *= 0.125f; q4[t].w *= 0.125f;
        }

        for (int kt = sp; kt <= qb; kt += NSPLIT) {
            const float* kb = qkv + (size_t)(b*TT + kt*64) * DQKV + DD + h*HD;
            const float* vb = kb + DD;
            __syncthreads();
            #pragma unroll
            for (int c = 0; c < 8; c++) {
                int f = c * 128 + tid;
                int row = f >> 4, col = f & 15;
                Ks[f] = *(const float4*)(kb + (size_t)row * DQKV + col * 4);
                Vs[f] = *(const float4*)(vb + (size_t)row * DQKV + col * 4);
            }
            __syncthreads();

            int jm = qwmax - kt*64 + 1;
            if (jm > 64) jm = 64;
            for (int j = 0; j < jm; j++) {
                const float4* kr = &Ks[j * 16];
                float sA, sB, sC, sD;
                sA  = dot4(q4[0], kr[0 + par]);
                sB  = dot4(q4[1], kr[2 + par]);
                sC  = dot4(q4[2], kr[4 + par]);
                sD  = dot4(q4[3], kr[6 + par]);
                sA += dot4(q4[4], kr[8 + par]);
                sB += dot4(q4[5], kr[10 + par]);
                sC += dot4(q4[6], kr[12 + par]);
                sD += dot4(q4[7], kr[14 + par]);
                float s = (sA + sB) + (sC + sD);
                s += __shfl_xor_sync(0xffffffffu, s, 1);

                int rel = kt*64 + j;
                bool ok = (rel <= q);
                float p;
                if (ok && s > mmax) {
                    float corr = __expf(mmax - s);
                    #pragma unroll
                    for (int i = 0; i < 8; i++) {
                        a4[i].x *= corr; a4[i].y *= corr;
                        a4[i].z *= corr; a4[i].w *= corr;
                    }
                    lsum *= corr; mmax = s; p = 1.f;
                } else {
                    p = ok ? __expf(s - mmax) : 0.f;
                }
                lsum += p;

                const float4* vr = &Vs[j * 16];
                #pragma unroll
                for (int t = 0; t < 8; t++) {
                    float4 vv = vr[2*t + par];
                    a4[t].x = fmaf(p, vv.x, a4[t].x);
                    a4[t].y = fmaf(p, vv.y, a4[t].y);
                    a4[t].z = fmaf(p, vv.z, a4[t].z);
                    a4[t].w = fmaf(p, vv.w, a4[t].w);
                }
            }
        }
    }

    size_t ab = ((size_t)sp * NTOK + tok) * DD + h * HD;
    #pragma unroll
    for (int t = 0; t < 8; t++)
        *(float4*)&pacc[ab + (2*t + par) * 4] = a4[t];
    if (par == 0) {
        size_t mi = ((size_t)sp * NTOK + tok) * HH + h;
        pm[mi] = mmax;
        pl[mi] = lsum;
    }
}

// Merge NSPLIT partials -> bf16 hi/lo attention output.
__global__ __launch_bounds__(64)
void attn_merge(const float* __restrict__ pacc, const float* __restrict__ pm,
                const float* __restrict__ pl,
                __nv_bfloat16* __restrict__ oh, __nv_bfloat16* __restrict__ ol) {
    int tokh = blockIdx.x;
    int tok = tokh / HH, h = tokh % HH;
    int d = threadIdx.x;

    float m[NSPLIT], l[NSPLIT];
    float M = -1e30f;
    #pragma unroll
    for (int s = 0; s < NSPLIT; s++) {
        size_t mi = ((size_t)s * NTOK + tok) * HH + h;
        m[s] = pm[mi]; l[s] = pl[mi];
        M = fmaxf(M, m[s]);
    }
    float L = 0.f, w[NSPLIT];
    #pragma unroll
    for (int s = 0; s < NSPLIT; s++) {
        w[s] = __expf(m[s] - M);
        L = fmaf(l[s], w[s], L);
    }
    float v = 0.f;
    #pragma unroll
    for (int s = 0; s < NSPLIT; s++) {
        size_t ab = ((size_t)s * NTOK + tok) * DD + h * HD + d;
        v = fmaf(pacc[ab], w[s], v);
    }
    float f = v / L;
    size_t ob = (size_t)tok * DD + h * HD + d;
    __nv_bfloat16 hh = __float2bfloat16(f);
    oh[ob] = hh;
    ol[ob] = __float2bfloat16(f - __bfloat162float(hh));
}

// ---------------- Driver ---------------------------
extern "C" void kernel_launch(void* const* d_in, const int* in_sizes, int n_in,
                              void* d_out, int out_size) {
    (void)in_sizes; (void)n_in; (void)out_size;
    const int*   x       = (const int*)  d_in[0];
    const float* tok_emb = (const float*)d_in[1];
    const float* pos_emb = (const float*)d_in[2];
    const float* qkv_w   = (const float*)d_in[3];
    const float* fc_w    = (const float*)d_in[4];
    const float* fc_b    = (const float*)d_in[5];
    const float* ln1_s   = (const float*)d_in[6];
    const float* ln1_b   = (const float*)d_in[7];
    const float* ln2_s   = (const float*)d_in[8];
    const float* ln2_b   = (const float*)d_in[9];
    const float* ff1_w   = (const float*)d_in[10];
    const float* ff1_b   = (const float*)d_in[11];
    const float* ff2_w   = (const float*)d_in[12];
    const float* ff2_b   = (const float*)d_in[13];
    const float* lnf_s   = (const float*)d_in[14];
    const float* lnf_b   = (const float*)d_in[15];
    const float* out_w   = (const float*)d_in[16];
    const float* out_b   = (const float*)d_in[17];
    float* logits = (float*)d_out;

    cudaFuncSetAttribute(mm_kernel<1>, cudaFuncAttributeMaxDynamicSharedMemorySize, GEMM_SMEM);
    cudaFuncSetAttribute(mm96<0>, cudaFuncAttributeMaxDynamicSharedMemorySize, GEMM96_SMEM);
    cudaFuncSetAttribute(mm96<1>, cudaFuncAttributeMaxDynamicSharedMemorySize, GEMM96_SMEM);
    cudaFuncSetAttribute(mm96<2>, cudaFuncAttributeMaxDynamicSharedMemorySize, GEMM96_SMEM);
    cudaFuncSetAttribute(mm96<3>, cudaFuncAttributeMaxDynamicSharedMemorySize, GEMM96_SMEM);

    float *h, *qkvb, *pacc, *pmv, *plv;
    __nv_bfloat16 *xh, *xl, *ah, *al, *fh, *fl;
    __nv_bfloat16 *qh, *ql, *fch, *fcl, *f1h, *f1l, *f2h, *f2l, *oh, *ol;
    cudaGetSymbolAddress((void**)&h,    g_h);
    cudaGetSymbolAddress((void**)&qkvb, g_qkv);
    cudaGetSymbolAddress((void**)&pacc, g_pacc);
    cudaGetSymbolAddress((void**)&pmv,  g_pm);
    cudaGetSymbolAddress((void**)&plv,  g_pl);
    cudaGetSymbolAddress((void**)&xh, g_xh);  cudaGetSymbolAddress((void**)&xl, g_xl);
    cudaGetSymbolAddress((void**)&ah, g_ah);  cudaGetSymbolAddress((void**)&al, g_al);
    cudaGetSymbolAddress((void**)&fh, g_fh);  cudaGetSymbolAddress((void**)&fl, g_fl);
    cudaGetSymbolAddress((void**)&qh, w_qkvh); cudaGetSymbolAddress((void**)&ql, w_qkvl);
    cudaGetSymbolAddress((void**)&fch, w_fch); cudaGetSymbolAddress((void**)&fcl, w_fcl);
    cudaGetSymbolAddress((void**)&f1h, w_f1h); cudaGetSymbolAddress((void**)&f1l, w_f1l);
    cudaGetSymbolAddress((void**)&f2h, w_f2h); cudaGetSymbolAddress((void**)&f2l, w_f2l);
    cudaGetSymbolAddress((void**)&oh, w_oh);   cudaGetSymbolAddress((void**)&ol, w_ol);

    cvt_kernel<<<2048, 256>>>(qkv_w, qh, ql, LL*DQKV*DD/4);
    cvt_kernel<<<1024, 256>>>(fc_w,  fch, fcl, LL*DD*DD/4);
    cvt_kernel<<<2048, 256>>>(ff1_w, f1h, f1l, LL*DFF*DD/4);
    cvt_kernel<<<2048, 256>>>(ff2_w, f2h, f2l, LL*DD*DFF/4);
    cvt_kernel<<<4096, 256>>>(out_w, oh, ol, VV*DD/4);

    embed_kernel<<<NTOK, 256>>>(x, tok_emb, pos_emb);

    for (int l = 0; l < LL; l++) {
        const __nv_bfloat16* wqh = qh + (size_t)l * DQKV * DD;
        const __nv_bfloat16* wql = ql + (size_t)l * DQKV * DD;
        const __nv_bfloat16* wph = fch + (size_t)l * DD * DD;
        const __nv_bfloat16* wpl = fcl + (size_t)l * DD * DD;
        const __nv_bfloat16* w1h = f1h + (size_t)l * DFF * DD;
        const __nv_bfloat16* w1l = f1l + (size_t)l * DFF * DD;
        const __nv_bfloat16* w2h = f2h + (size_t)l * DD * DFF;
        const __nv_bfloat16* w2l = f2l + (size_t)l * DD * DFF;

        ln_kernel<<<NTOK, 256>>>(h, ln1_s + (size_t)l*DD, ln1_b + (size_t)l*DD, xh, xl);
        mm96<0><<<dim3(NTOK/128, DQKV/N96), 256, GEMM96_SMEM>>>(
            xh, xl, wqh, wql, nullptr, qkvb, nullptr, nullptr, DQKV, DD);
        attn_kernel<<<dim3(TT/64, BB*HH, NSPLIT), 128>>>(qkvb, pacc, pmv, plv);
        attn_merge<<<NTOK*HH, 64>>>(pacc, pmv, plv, ah, al);
        mm96<2><<<dim3(NTOK/128, DD/N96), 256, GEMM96_SMEM>>>(
            ah, al, wph, wpl, fc_b + (size_t)l*DD, h, nullptr, nullptr, DD, DD);
        ln_kernel<<<NTOK, 256>>>(h, ln2_s + (size_t)l*DD, ln2_b + (size_t)l*DD, xh, xl);
        mm96<3><<<dim3(NTOK/128, DFF/N96), 256, GEMM96_SMEM>>>(
            xh, xl, w1h, w1l, ff1_b + (size_t)l*DFF, nullptr, fh, fl, DFF, DD);
        mm96<2><<<dim3(NTOK/128, DD/N96), 256, GEMM96_SMEM>>>(
            fh, fl, w2h, w2l, ff2_b + (size_t)l*DD, h, nullptr, nullptr, DD, DFF);
    }

    ln_kernel<<<NTOK, 256>>>(h, lnf_s, lnf_b, xh, xl);
    // Vocab projection: 96-wide main body [0, 31968) + 64-wide tail [31936, 32000).
    // Overlap columns [31936, 31968) are written twice with identical values.
    mm96<1><<<dim3(NTOK/128, 333), 256, GEMM96_SMEM>>>(
        xh, xl, oh, ol, out_b, logits, nullptr, nullptr, VV, DD);
    mm_kernel<1><<<dim3(NTOK/128, 1), 256, GEMM_SMEM>>>(
        xh, xl, oh + (size_t)(VV - 64) * DD, ol + (size_t)(VV - 64) * DD,
        out_b + (VV - 64), logits + (VV - 64), nullptr, nullptr, VV, DD);
}